// round 11
// baseline (speedup 1.0000x reference)
#include <cuda_runtime.h>
#include <stdint.h>

// QuantEmbedding fused: out[0:rows*dim] = gather(QIL_quantize(W,p,c), x),
// out[rows*dim] = s = 127/(c-p), out[rows*dim+1] = p = max(pp,0).
//
// Non-persistent multirow kernel: block = 192 threads (= dim4), each block
// handles 8 rows. Thread tid <-> float4 tid of each row (warp-contiguous,
// 4 lines per LDG.128), 8 independent coalesced loads per thread (MLP=8),
// pure 32-bit address arithmetic (all element offsets < 2^31).
// Writes evict-first (__stcs): the 50MB output stream is single-use.

__device__ __forceinline__ float qil_one(float w, float p, float s, float inv_s) {
    // |w|<p => (|w|-p)*s < 0 => q <= 0, folded into the q>0 select.
    float aw = fabsf(w);
    float q  = rintf(fminf((aw - p) * s, 127.0f));
    float r  = copysignf(fmaf(q, inv_s, p), w);
    return (q > 0.0f) ? r : 0.0f;
}

__device__ __forceinline__ float4 qil_vec(float4 v, float p, float s, float inv_s) {
    float4 r;
    r.x = qil_one(v.x, p, s, inv_s);
    r.y = qil_one(v.y, p, s, inv_s);
    r.z = qil_one(v.z, p, s, inv_s);
    r.w = qil_one(v.w, p, s, inv_s);
    return r;
}

template <int DIM4, int RPB>
__global__ __launch_bounds__(DIM4)
void qembed_multirow8_kernel(const int* __restrict__ x,
                             const float4* __restrict__ w4,
                             const float* __restrict__ pp,
                             const float* __restrict__ cp,
                             float4* __restrict__ out4,
                             int rows,
                             unsigned int scalar_base, int n_scalars) {
    const unsigned int tid  = threadIdx.x;
    const int          row0 = (int)blockIdx.x * RPB;

    const float p = fmaxf(__ldg(&pp[0]), 0.0f);
    const float c = __ldg(&cp[0]);
    const float s = 127.0f / (c - p);
    const float inv_s = 1.0f / s;

    if (blockIdx.x == 0 && tid == 0 && n_scalars > 0) {
        float* out = (float*)out4;
        out[scalar_base] = s;
        if (n_scalars >= 2) out[scalar_base + 1] = p;
    }

    if (row0 + RPB <= rows) {
        // Full group: RPB token ids, then RPB independent coalesced loads.
        unsigned int src[RPB];
#pragma unroll
        for (int r = 0; r < RPB; r++) {
            int tok = __ldg(&x[row0 + r]);
            src[r] = (unsigned int)tok * (unsigned int)DIM4 + tid;
        }

        float4 v[RPB];
#pragma unroll
        for (int r = 0; r < RPB; r++)       // MLP = RPB
            v[r] = w4[src[r]];

        unsigned int dst = (unsigned int)row0 * (unsigned int)DIM4 + tid;
#pragma unroll
        for (int r = 0; r < RPB; r++) {
            __stcs(&out4[dst], qil_vec(v[r], p, s, inv_s));
            dst += DIM4;
        }
    } else {
        // Ragged tail group.
        for (int r = 0; r < RPB; r++) {
            const int row = row0 + r;
            if (row >= rows) break;
            int tok = __ldg(&x[row]);
            float4 v = w4[(unsigned int)tok * (unsigned int)DIM4 + tid];
            __stcs(&out4[(unsigned int)row * (unsigned int)DIM4 + tid],
                   qil_vec(v, p, s, inv_s));
        }
    }
}

// Generic fallback (arbitrary dim divisible by 4): one row per block.
__global__ __launch_bounds__(256)
void qembed_row_kernel(const int* __restrict__ x,
                       const float4* __restrict__ w4,
                       const float* __restrict__ pp,
                       const float* __restrict__ cp,
                       float4* __restrict__ out4,
                       int dim4, long long scalar_base, int n_scalars) {
    const int row = blockIdx.x;
    const int tok = __ldg(&x[row]);
    const float p = fmaxf(__ldg(&pp[0]), 0.0f);
    const float c = __ldg(&cp[0]);
    const float s = 127.0f / (c - p);
    const float inv_s = 1.0f / s;
    const long long src_base = (long long)tok * dim4;
    const long long dst_base = (long long)row * dim4;
    for (int j = threadIdx.x; j < dim4; j += blockDim.x) {
        float4 v = w4[src_base + j];
        __stcs(&out4[dst_base + j], qil_vec(v, p, s, inv_s));
    }
    if (blockIdx.x == 0 && threadIdx.x == 0 && n_scalars > 0) {
        float* out = (float*)out4;
        out[scalar_base] = s;
        if (n_scalars >= 2) out[scalar_base + 1] = p;
    }
}

extern "C" void kernel_launch(void* const* d_in, const int* in_sizes, int n_in,
                              void* d_out, int out_size) {
    const int*   x  = (const int*)d_in[0];          // [batch*seq] token ids
    const float* w  = (const float*)d_in[1];        // [vocab, dim] float32
    const float* pp = (const float*)d_in[2];        // [1]
    const float* cp = (const float*)d_in[3];        // [1]

    const int rows = in_sizes[0];                   // 16384

    // Derive dim and scalar-tail count from out_size.
    long long dim;
    int n_scalars;
    long long osz = (long long)out_size;
    if (rows > 0 && (osz - 2) > 0 && (osz - 2) % rows == 0) {
        dim = (osz - 2) / rows;  n_scalars = 2;     // expected: 768, 2
    } else if (rows > 0 && (osz - 1) > 0 && (osz - 1) % rows == 0) {
        dim = (osz - 1) / rows;  n_scalars = 1;
    } else {
        dim = (rows > 0) ? osz / rows : 0;  n_scalars = 0;
    }

    const int dim4 = (int)(dim / 4);
    const long long scalar_base = (long long)rows * dim;

    // 32-bit-safe fast path: dim4==192 and all element offsets < 2^31.
    if (dim4 == 192 && scalar_base + 2 < 0x7FFFFFFFLL) {
        constexpr int RPB = 8;
        const int blocks = (rows + RPB - 1) / RPB;   // 2048
        qembed_multirow8_kernel<192, RPB><<<blocks, 192>>>(
            x, (const float4*)w, pp, cp, (float4*)d_out,
            rows, (unsigned int)scalar_base, n_scalars);
    } else if ((dim % 4) == 0 && dim4 > 0) {
        int threads = dim4 < 256 ? ((dim4 + 31) / 32) * 32 : 256;
        if (threads < 32) threads = 32;
        qembed_row_kernel<<<rows, threads>>>(
            x, (const float4*)w, pp, cp, (float4*)d_out,
            dim4, scalar_base, n_scalars);
    }
}

// round 13
// speedup vs baseline: 1.0111x; 1.0111x over previous
#include <cuda_runtime.h>
#include <stdint.h>

// QuantEmbedding fused: out[0:rows*dim] = gather(QIL_quantize(W,p,c), x),
// out[rows*dim] = s = 127/(c-p), out[rows*dim+1] = p = max(pp,0).
//
// Converged configuration (DRAM-traffic-pinned at ~7 TB/s steady state):
//  - block = 192 threads (= dim4), each block handles 4 rows
//  - thread tid <-> float4 tid of each row: warp-contiguous LDG.128/STG.128
//  - 4 independent row loads per thread (MLP=4)
//  - weight reads default-cached (L2 retains the ~44MB unique row set across
//    graph replays; intra-iteration duplicate rows also hit)
//  - output writes evict-first (__stcs): 50MB single-use stream
//  - pure 32-bit address arithmetic (all element offsets < 2^31)
//  - scalar tail fused into block 0

__device__ __forceinline__ float qil_one(float w, float p, float s, float inv_s) {
    // |w|<p => (|w|-p)*s < 0 => q <= 0, folded into the q>0 select.
    float aw = fabsf(w);
    float q  = rintf(fminf((aw - p) * s, 127.0f));
    float r  = copysignf(fmaf(q, inv_s, p), w);
    return (q > 0.0f) ? r : 0.0f;
}

__device__ __forceinline__ float4 qil_vec(float4 v, float p, float s, float inv_s) {
    float4 r;
    r.x = qil_one(v.x, p, s, inv_s);
    r.y = qil_one(v.y, p, s, inv_s);
    r.z = qil_one(v.z, p, s, inv_s);
    r.w = qil_one(v.w, p, s, inv_s);
    return r;
}

template <int DIM4, int RPB>
__global__ __launch_bounds__(DIM4)
void qembed_multirow_kernel(const int* __restrict__ x,
                            const float4* __restrict__ w4,
                            const float* __restrict__ pp,
                            const float* __restrict__ cp,
                            float4* __restrict__ out4,
                            int rows,
                            unsigned int scalar_base, int n_scalars) {
    const unsigned int tid  = threadIdx.x;
    const int          row0 = (int)blockIdx.x * RPB;

    const float p = fmaxf(__ldg(&pp[0]), 0.0f);
    const float c = __ldg(&cp[0]);
    const float s = 127.0f / (c - p);
    const float inv_s = 1.0f / s;

    if (blockIdx.x == 0 && tid == 0 && n_scalars > 0) {
        float* out = (float*)out4;
        out[scalar_base] = s;
        if (n_scalars >= 2) out[scalar_base + 1] = p;
    }

    if (row0 + RPB <= rows) {
        unsigned int src[RPB];
#pragma unroll
        for (int r = 0; r < RPB; r++) {
            int tok = __ldg(&x[row0 + r]);
            src[r] = (unsigned int)tok * (unsigned int)DIM4 + tid;
        }

        float4 v[RPB];
#pragma unroll
        for (int r = 0; r < RPB; r++)       // MLP = RPB independent coalesced loads
            v[r] = w4[src[r]];

        unsigned int dst = (unsigned int)row0 * (unsigned int)DIM4 + tid;
#pragma unroll
        for (int r = 0; r < RPB; r++) {
            __stcs(&out4[dst], qil_vec(v[r], p, s, inv_s));
            dst += DIM4;
        }
    } else {
        // Ragged tail group.
        for (int r = 0; r < RPB; r++) {
            const int row = row0 + r;
            if (row >= rows) break;
            int tok = __ldg(&x[row]);
            float4 v = w4[(unsigned int)tok * (unsigned int)DIM4 + tid];
            __stcs(&out4[(unsigned int)row * (unsigned int)DIM4 + tid],
                   qil_vec(v, p, s, inv_s));
        }
    }
}

// Generic fallback (arbitrary dim divisible by 4): one row per block.
__global__ __launch_bounds__(256)
void qembed_row_kernel(const int* __restrict__ x,
                       const float4* __restrict__ w4,
                       const float* __restrict__ pp,
                       const float* __restrict__ cp,
                       float4* __restrict__ out4,
                       int dim4, long long scalar_base, int n_scalars) {
    const int row = blockIdx.x;
    const int tok = __ldg(&x[row]);
    const float p = fmaxf(__ldg(&pp[0]), 0.0f);
    const float c = __ldg(&cp[0]);
    const float s = 127.0f / (c - p);
    const float inv_s = 1.0f / s;
    const long long src_base = (long long)tok * dim4;
    const long long dst_base = (long long)row * dim4;
    for (int j = threadIdx.x; j < dim4; j += blockDim.x) {
        float4 v = w4[src_base + j];
        __stcs(&out4[dst_base + j], qil_vec(v, p, s, inv_s));
    }
    if (blockIdx.x == 0 && threadIdx.x == 0 && n_scalars > 0) {
        float* out = (float*)out4;
        out[scalar_base] = s;
        if (n_scalars >= 2) out[scalar_base + 1] = p;
    }
}

extern "C" void kernel_launch(void* const* d_in, const int* in_sizes, int n_in,
                              void* d_out, int out_size) {
    const int*   x  = (const int*)d_in[0];          // [batch*seq] token ids
    const float* w  = (const float*)d_in[1];        // [vocab, dim] float32
    const float* pp = (const float*)d_in[2];        // [1]
    const float* cp = (const float*)d_in[3];        // [1]

    const int rows = in_sizes[0];                   // 16384

    // Derive dim and scalar-tail count from out_size.
    long long dim;
    int n_scalars;
    long long osz = (long long)out_size;
    if (rows > 0 && (osz - 2) > 0 && (osz - 2) % rows == 0) {
        dim = (osz - 2) / rows;  n_scalars = 2;     // expected: 768, 2
    } else if (rows > 0 && (osz - 1) > 0 && (osz - 1) % rows == 0) {
        dim = (osz - 1) / rows;  n_scalars = 1;
    } else {
        dim = (rows > 0) ? osz / rows : 0;  n_scalars = 0;
    }

    const int dim4 = (int)(dim / 4);
    const long long scalar_base = (long long)rows * dim;

    // 32-bit-safe fast path: dim4==192 and all element offsets < 2^31.
    if (dim4 == 192 && scalar_base + 2 < 0x7FFFFFFFLL) {
        constexpr int RPB = 4;
        const int blocks = (rows + RPB - 1) / RPB;   // 4096
        qembed_multirow_kernel<192, RPB><<<blocks, 192>>>(
            x, (const float4*)w, pp, cp, (float4*)d_out,
            rows, (unsigned int)scalar_base, n_scalars);
    } else if ((dim % 4) == 0 && dim4 > 0) {
        int threads = dim4 < 256 ? ((dim4 + 31) / 32) * 32 : 256;
        if (threads < 32) threads = 32;
        qembed_row_kernel<<<rows, threads>>>(
            x, (const float4*)w, pp, cp, (float4*)d_out,
            dim4, scalar_base, n_scalars);
    }
}